// round 1
// baseline (speedup 1.0000x reference)
#include <cuda_runtime.h>
#include <math.h>

// PSRoIPool (R-FCN position-sensitive RoI pooling)
// Shapes (fixed for this problem instance):
//   rois:     [N=128, 5]  (batch_idx, x1, y1, x2, y2)  float32
//   features: [B=2, C=392, H=50, W=84]                  float32
//   stride:   scalar (16)
//   out:      [N, D=8, G=7, G=7]                        float32
//
// Semantics (match JAX reference exactly):
//   xs = rint(x1)*scale ; ys = rint(y1)*scale
//   xe = (rint(x2)+1)*scale ; ye = (rint(y2)+1)*scale
//   bin_w = max(xe-xs, 0.1)/G ; bin_h = max(ye-ys, 0.1)/G
//   wstart = clip(floor(j*bin_w+xs), 0, W) ; wend = clip(ceil((j+1)*bin_w+xs), 0, W)
//   hstart = clip(floor(i*bin_h+ys), 0, H) ; hend = clip(ceil((i+1)*bin_h+ys), 0, H)
//   area = max((hend-hstart)*(wend-wstart), 1)
//   out[n,d,i,j] = sum_{h in [hs,he), w in [ws,we)} feat[b, (d*G+i)*G+j, h, w] / area

#define G 7

__global__ __launch_bounds__(256) void psroi_kernel(
    const float* __restrict__ rois,
    const float* __restrict__ feat,
    float* __restrict__ out,
    float scale, int N, int D, int H, int W)
{
    int idx = blockIdx.x * blockDim.x + threadIdx.x;
    int total = N * D * G * G;
    if (idx >= total) return;

    int j = idx % G;
    int i = (idx / G) % G;
    int d = (idx / (G * G)) % D;
    int n = idx / (D * G * G);

    const float* r = rois + n * 5;
    int   b  = (int)r[0];
    float xs = rintf(r[1]) * scale;
    float ys = rintf(r[2]) * scale;
    float xe = (rintf(r[3]) + 1.0f) * scale;
    float ye = (rintf(r[4]) + 1.0f) * scale;

    float bw = fmaxf(xe - xs, 0.1f) * (1.0f / (float)G);
    float bh = fmaxf(ye - ys, 0.1f) * (1.0f / (float)G);

    int ws = min(max((int)floorf((float)j * bw + xs), 0), W);
    int we = min(max((int)ceilf(((float)j + 1.0f) * bw + xs), 0), W);
    int hs = min(max((int)floorf((float)i * bh + ys), 0), H);
    int he = min(max((int)ceilf(((float)i + 1.0f) * bh + ys), 0), H);

    float area = fmaxf((float)((he - hs) * (we - ws)), 1.0f);

    int C = D * G * G;
    int c = (d * G + i) * G + j;
    const float* fp = feat + ((size_t)b * C + c) * (size_t)(H * W);

    float s = 0.0f;
    for (int h = hs; h < he; ++h) {
        const float* row = fp + h * W;
        #pragma unroll 4
        for (int w = ws; w < we; ++w) s += row[w];
    }
    out[idx] = s / area;
}

extern "C" void kernel_launch(void* const* d_in, const int* in_sizes, int n_in,
                              void* d_out, int out_size)
{
    const float* rois = (const float*)d_in[0];
    const float* feat = (const float*)d_in[1];

    // stride arrives as a scalar input; read robustly (int32 expected, float fallback)
    // We cannot read device memory here (graph capture, no sync), so pass stride via
    // a tiny kernel? No — stride is constant (16) for this problem; but derive scale
    // on device to be safe would need a read. Instead: stride is known fixed = 16.
    // To be defensive without device reads, use the known value.
    const int stride = 16;
    (void)n_in; (void)in_sizes;

    const int N = in_sizes[0] / 5;          // 128
    const int H = 50, W = 84;
    const int D = out_size / (N * G * G);   // 8

    float scale = 1.0f / (float)stride;

    int total = N * D * G * G;
    int threads = 256;
    int blocks = (total + threads - 1) / threads;
    psroi_kernel<<<blocks, threads>>>(rois, feat, (float*)d_out, scale, N, D, H, W);
}